// round 6
// baseline (speedup 1.0000x reference)
#include <cuda_runtime.h>

#define FIN 512
#define HID 64
#define NCLS 40

// Scratch (no allocs allowed): two 25.6MB ping-pong buffers.
__device__ float g_buf1[6400000];
__device__ float g_buf2[6400000];

// ---------------------------------------------------------------- utilities
__global__ void zero_buf2(int n4) {
    int i = blockIdx.x * blockDim.x + threadIdx.x;
    if (i < n4) ((float4*)g_buf2)[i] = make_float4(0.f, 0.f, 0.f, 0.f);
}

// ------------------------------------------------- GEMM1: Y = x @ W1 (fp32 SIMT)
#define G1_BM 128
#define G1_BK 16
#define G1_ASTR 132
#define G1_BSTR 68

__global__ __launch_bounds__(256) void gemm1_kernel(const float* __restrict__ X,
                                                    const float* __restrict__ W,
                                                    int nrows) {
    __shared__ float As[G1_BK * G1_ASTR];  // k-major: As[k][m]
    __shared__ float Bs[G1_BK * G1_BSTR];  // Bs[k][n]
    const int tid = threadIdx.x;
    const int bm = blockIdx.x * G1_BM;
    const int tx = tid & 15;
    const int ty = tid >> 4;

    float acc[8][4];
#pragma unroll
    for (int i = 0; i < 8; ++i)
#pragma unroll
        for (int j = 0; j < 4; ++j) acc[i][j] = 0.f;

    for (int k0 = 0; k0 < FIN; k0 += G1_BK) {
#pragma unroll
        for (int p = 0; p < 2; ++p) {
            int i = p * 256 + tid;
            int r = i >> 2;
            int kq = (i & 3) * 4;
            int gr = bm + r;
            float4 v = (gr < nrows)
                           ? __ldg((const float4*)(X + (size_t)gr * FIN + k0 + kq))
                           : make_float4(0.f, 0.f, 0.f, 0.f);
            As[(kq + 0) * G1_ASTR + r] = v.x;
            As[(kq + 1) * G1_ASTR + r] = v.y;
            As[(kq + 2) * G1_ASTR + r] = v.z;
            As[(kq + 3) * G1_ASTR + r] = v.w;
        }
        {
            int r = tid >> 4;
            int c4 = (tid & 15) * 4;
            float4 v = __ldg((const float4*)(W + (size_t)(k0 + r) * HID + c4));
            *(float4*)(Bs + r * G1_BSTR + c4) = v;
        }
        __syncthreads();

#pragma unroll
        for (int k = 0; k < G1_BK; ++k) {
            float4 b = *(const float4*)(Bs + k * G1_BSTR + tx * 4);
            float a[8];
#pragma unroll
            for (int q = 0; q < 8; ++q) a[q] = As[k * G1_ASTR + ty * 8 + q];
#pragma unroll
            for (int q = 0; q < 8; ++q) {
                acc[q][0] += a[q] * b.x;
                acc[q][1] += a[q] * b.y;
                acc[q][2] += a[q] * b.z;
                acc[q][3] += a[q] * b.w;
            }
        }
        __syncthreads();
    }

#pragma unroll
    for (int q = 0; q < 8; ++q) {
        int gr = bm + ty * 8 + q;
        if (gr < nrows)
            *(float4*)(g_buf1 + (size_t)gr * HID + tx * 4) =
                make_float4(acc[q][0], acc[q][1], acc[q][2], acc[q][3]);
    }
}

// ------------------------------------------------- SpMM (64-wide): scatter-add
__global__ void spmm_hid(const int* __restrict__ er, const int* __restrict__ ec,
                         const float* __restrict__ ev, int E) {
    int gt = blockIdx.x * blockDim.x + threadIdx.x;
    int e = gt >> 4;
    if (e >= E) return;
    int s = (gt & 15) * 4;
    float v = __ldg(ev + e);
    int col = __ldg(ec + e);
    int row = __ldg(er + e);
    float4 a = *(const float4*)(g_buf1 + (size_t)col * HID + s);
    float4 d = make_float4(a.x * v, a.y * v, a.z * v, a.w * v);
#if __CUDA_ARCH__ >= 900
    atomicAdd((float4*)(g_buf2 + (size_t)row * HID + s), d);
#else
    float* p = g_buf2 + (size_t)row * HID + s;
    atomicAdd(p + 0, d.x); atomicAdd(p + 1, d.y);
    atomicAdd(p + 2, d.z); atomicAdd(p + 3, d.w);
#endif
}

// ------ bias + relu + JAX PARTITIONABLE-threefry dropout (key=42, p=0.5)
// jax_threefry_partitionable=True (modern default): element i draws bits via
// threefry2x32(key, (hi32(i), lo32(i))) and XOR-folds the two output words.
__global__ void bias_relu_dropout(const float* __restrict__ b1, int total) {
    int j = blockIdx.x * blockDim.x + threadIdx.x;
    if (j >= total) return;
    unsigned x0 = 0u, x1 = (unsigned)j;  // counts_hi = 0, counts_lo = j
    const unsigned ks0 = 0u, ks1 = 42u, ks2 = 0x1BD11BDAu ^ 42u;
    x0 += ks0; x1 += ks1;
#define TF_ROUND(r) { x0 += x1; x1 = __funnelshift_l(x1, x1, r); x1 ^= x0; }
    TF_ROUND(13) TF_ROUND(15) TF_ROUND(26) TF_ROUND(6)
    x0 += ks1; x1 += ks2 + 1u;
    TF_ROUND(17) TF_ROUND(29) TF_ROUND(16) TF_ROUND(24)
    x0 += ks2; x1 += ks0 + 2u;
    TF_ROUND(13) TF_ROUND(15) TF_ROUND(26) TF_ROUND(6)
    x0 += ks0; x1 += ks1 + 3u;
    TF_ROUND(17) TF_ROUND(29) TF_ROUND(16) TF_ROUND(24)
    x0 += ks1; x1 += ks2 + 4u;
    TF_ROUND(13) TF_ROUND(15) TF_ROUND(26) TF_ROUND(6)
    x0 += ks2; x1 += ks0 + 5u;
#undef TF_ROUND
    unsigned w = x0 ^ x1;  // 32-bit draw = xor-fold of the two output words
    // keep = uniform<0.5  <=>  MSB(bits)==0
    int f = j & (HID - 1);
    float b = __ldg(b1 + f);
    float v0 = g_buf2[j] + b;
    v0 = fmaxf(v0, 0.f);
    v0 = (w >> 31) ? 0.f : v0 * 2.f;
    g_buf2[j] = v0;
}

// ------------------------------------------------- GEMM2: G = h @ W2 (fp32)
__global__ __launch_bounds__(320) void gemm2_kernel(const float* __restrict__ W2, int nrows) {
    __shared__ float sH[128 * 68];
    __shared__ float sW[HID * NCLS];
    const int tid = threadIdx.x;
    const int bm = blockIdx.x * 128;
    for (int i = tid; i < HID * NCLS; i += 320) sW[i] = __ldg(W2 + i);
    for (int i = tid; i < 2048; i += 320) {
        int r = i >> 4, c4 = (i & 15) * 4, gr = bm + r;
        float4 v = (gr < nrows) ? *(const float4*)(g_buf2 + (size_t)gr * HID + c4)
                                : make_float4(0.f, 0.f, 0.f, 0.f);
        *(float4*)(sH + r * 68 + c4) = v;
    }
    __syncthreads();
    const int rg = tid / 10;
    const int cg = tid - rg * 10;
    float acc[4][4];
#pragma unroll
    for (int a = 0; a < 4; ++a)
#pragma unroll
        for (int b = 0; b < 4; ++b) acc[a][b] = 0.f;
#pragma unroll 8
    for (int k = 0; k < HID; ++k) {
        float4 w = *(const float4*)(sW + k * NCLS + cg * 4);
#pragma unroll
        for (int jr = 0; jr < 4; ++jr) {
            float a = sH[(rg * 4 + jr) * 68 + k];
            acc[jr][0] += a * w.x; acc[jr][1] += a * w.y;
            acc[jr][2] += a * w.z; acc[jr][3] += a * w.w;
        }
    }
#pragma unroll
    for (int jr = 0; jr < 4; ++jr) {
        int gr = bm + rg * 4 + jr;
        if (gr < nrows)
            *(float4*)(g_buf1 + (size_t)gr * NCLS + cg * 4) =
                make_float4(acc[jr][0], acc[jr][1], acc[jr][2], acc[jr][3]);
    }
}

// ------------------------------------------------- SpMM (40-wide): scatter-add
__global__ void spmm_cls(const int* __restrict__ er, const int* __restrict__ ec,
                         const float* __restrict__ ev, int E) {
    int gt = blockIdx.x * blockDim.x + threadIdx.x;
    int e = gt / 10;
    if (e >= E) return;
    int s = (gt - e * 10) * 4;
    float v = __ldg(ev + e);
    int col = __ldg(ec + e);
    int row = __ldg(er + e);
    float4 a = *(const float4*)(g_buf1 + (size_t)col * NCLS + s);
    float4 d = make_float4(a.x * v, a.y * v, a.z * v, a.w * v);
#if __CUDA_ARCH__ >= 900
    atomicAdd((float4*)(g_buf2 + (size_t)row * NCLS + s), d);
#else
    float* p = g_buf2 + (size_t)row * NCLS + s;
    atomicAdd(p + 0, d.x); atomicAdd(p + 1, d.y);
    atomicAdd(p + 2, d.z); atomicAdd(p + 3, d.w);
#endif
}

// ------------------------------------------------- +b2, log_softmax, write out
__global__ void lsm_kernel(const float* __restrict__ b2, float* __restrict__ out, int nrows) {
    int warp = threadIdx.x >> 5;
    int lane = threadIdx.x & 31;
    int row = blockIdx.x * 8 + warp;
    if (row >= nrows) return;
    const float* z = g_buf2 + (size_t)row * NCLS;
    float v0 = z[lane] + __ldg(b2 + lane);
    float v1 = -3.4e38f;
    if (lane < 8) v1 = z[32 + lane] + __ldg(b2 + 32 + lane);
    float m = fmaxf(v0, v1);
#pragma unroll
    for (int o = 16; o; o >>= 1) m = fmaxf(m, __shfl_xor_sync(0xffffffffu, m, o));
    float s = expf(v0 - m) + ((lane < 8) ? expf(v1 - m) : 0.f);
#pragma unroll
    for (int o = 16; o; o >>= 1) s += __shfl_xor_sync(0xffffffffu, s, o);
    float L = m + logf(s);
    out[(size_t)row * NCLS + lane] = v0 - L;
    if (lane < 8) out[(size_t)row * NCLS + 32 + lane] = v1 - L;
}

// ---------------------------------------------------------------- launcher
extern "C" void kernel_launch(void* const* d_in, const int* in_sizes, int n_in,
                              void* d_out, int out_size) {
    const float* x  = (const float*)d_in[0];
    const float* ev = (const float*)d_in[1];
    const float* W1 = (const float*)d_in[2];
    const float* b1 = (const float*)d_in[3];
    const float* W2 = (const float*)d_in[4];
    const float* b2 = (const float*)d_in[5];
    const int*   er = (const int*)d_in[6];
    const int*   ec = (const int*)d_in[7];
    const int nrows = in_sizes[0] / FIN;  // 100000
    const int E = in_sizes[1];            // 1000000
    float* out = (float*)d_out;

    int nh4 = nrows * HID / 4;
    zero_buf2<<<(nh4 + 255) / 256, 256>>>(nh4);
    gemm1_kernel<<<(nrows + G1_BM - 1) / G1_BM, 256>>>(x, W1, nrows);
    spmm_hid<<<(E * 16 + 255) / 256, 256>>>(er, ec, ev, E);
    int total = nrows * HID;
    bias_relu_dropout<<<(total + 255) / 256, 256>>>(b1, total);
    gemm2_kernel<<<(nrows + 127) / 128, 320>>>(W2, nrows);
    int nc4 = nrows * NCLS / 4;
    zero_buf2<<<(nc4 + 255) / 256, 256>>>(nc4);
    spmm_cls<<<(E * 10 + 255) / 256, 256>>>(er, ec, ev, E);
    lsm_kernel<<<(nrows + 7) / 8, 256>>>(b2, out, nrows);
}

// round 8
// speedup vs baseline: 1.3214x; 1.3214x over previous
#include <cuda_runtime.h>

#define FIN 512
#define HID 64
#define NCLS 40

// Scratch (no allocs allowed): two 25.6MB ping-pong buffers.
__device__ float g_buf1[6400000];
__device__ float g_buf2[6400000];

// ---------------------------------------------------------------- utilities
__global__ void zero_buf2(int n4) {
    int i = blockIdx.x * blockDim.x + threadIdx.x;
    if (i < n4) ((float4*)g_buf2)[i] = make_float4(0.f, 0.f, 0.f, 0.f);
}

// ------------------------------------------------- GEMM1: Y = x @ W1  (bf16x3 tensor core)
__device__ __forceinline__ void mma_bf16(float c[4], const unsigned a[4], const unsigned b[2]) {
    asm volatile(
        "mma.sync.aligned.m16n8k16.row.col.f32.bf16.bf16.f32 "
        "{%0,%1,%2,%3}, {%4,%5,%6,%7}, {%8,%9}, {%0,%1,%2,%3};"
        : "+f"(c[0]), "+f"(c[1]), "+f"(c[2]), "+f"(c[3])
        : "r"(a[0]), "r"(a[1]), "r"(a[2]), "r"(a[3]), "r"(b[0]), "r"(b[1]));
}

// pack (even,odd) fp32 pair into bf16x2 hi + bf16x2 lo (residual)
__device__ __forceinline__ void split2(float ve, float vo, unsigned &h, unsigned &l) {
    unsigned hh;
    asm("cvt.rn.bf16x2.f32 %0, %1, %2;" : "=r"(hh) : "f"(vo), "f"(ve));
    float fe = __uint_as_float(hh << 16);
    float fo = __uint_as_float(hh & 0xffff0000u);
    float re = ve - fe;
    float ro = vo - fo;
    unsigned ll;
    asm("cvt.rn.bf16x2.f32 %0, %1, %2;" : "=r"(ll) : "f"(ro), "f"(re));
    h = hh; l = ll;
}

#define AS_STRIDE 36
#define BS_STRIDE 76

__global__ __launch_bounds__(256) void gemm1_kernel(const float* __restrict__ X,
                                                    const float* __restrict__ W,
                                                    int nrows) {
    __shared__ float As[128 * AS_STRIDE];  // 128 rows x 32 k
    __shared__ float Bs[32 * BS_STRIDE];   // 32 k x 64 n
    const int tid = threadIdx.x;
    const int bm = blockIdx.x * 128;
    const int warp = tid >> 5, lane = tid & 31;
    const int g = lane >> 2, tg = lane & 3;
    const int wm = (warp >> 1) * 32;
    const int wn = (warp & 1) * 32;

    float c[2][4][4];
#pragma unroll
    for (int a = 0; a < 2; ++a)
#pragma unroll
        for (int b = 0; b < 4; ++b)
#pragma unroll
            for (int d = 0; d < 4; ++d) c[a][b][d] = 0.f;

    float4 ra[4], rb4[2];
    // prologue: load tile kt=0
#pragma unroll
    for (int p = 0; p < 4; ++p) {
        int i = p * 256 + tid, r = i >> 3, c4 = (i & 7) * 4, gr = bm + r;
        ra[p] = (gr < nrows) ? __ldg((const float4*)(X + (size_t)gr * FIN + c4))
                             : make_float4(0.f, 0.f, 0.f, 0.f);
    }
#pragma unroll
    for (int p = 0; p < 2; ++p) {
        int i = p * 256 + tid, r = i >> 4, c4 = (i & 15) * 4;
        rb4[p] = __ldg((const float4*)(W + (size_t)r * HID + c4));
    }
#pragma unroll
    for (int p = 0; p < 4; ++p) {
        int i = p * 256 + tid, r = i >> 3, c4 = (i & 7) * 4;
        *(float4*)(As + r * AS_STRIDE + c4) = ra[p];
    }
#pragma unroll
    for (int p = 0; p < 2; ++p) {
        int i = p * 256 + tid, r = i >> 4, c4 = (i & 15) * 4;
        *(float4*)(Bs + r * BS_STRIDE + c4) = rb4[p];
    }
    __syncthreads();

    for (int kt = 0; kt < FIN / 32; ++kt) {
        if (kt + 1 < FIN / 32) {  // prefetch next tile into registers
            int k0 = (kt + 1) * 32;
#pragma unroll
            for (int p = 0; p < 4; ++p) {
                int i = p * 256 + tid, r = i >> 3, c4 = (i & 7) * 4, gr = bm + r;
                ra[p] = (gr < nrows)
                            ? __ldg((const float4*)(X + (size_t)gr * FIN + k0 + c4))
                            : make_float4(0.f, 0.f, 0.f, 0.f);
            }
#pragma unroll
            for (int p = 0; p < 2; ++p) {
                int i = p * 256 + tid, r = i >> 4, c4 = (i & 15) * 4;
                rb4[p] = __ldg((const float4*)(W + (size_t)(k0 + r) * HID + c4));
            }
        }
#pragma unroll
        for (int kk = 0; kk < 2; ++kk) {
            const int kb = kk * 16;
            unsigned ah[2][4], al[2][4];
#pragma unroll
            for (int mt = 0; mt < 2; ++mt) {
                int r0 = wm + mt * 16 + g;
                float2 p0 = *(const float2*)(As + r0 * AS_STRIDE + kb + 2 * tg);
                float2 p1 = *(const float2*)(As + (r0 + 8) * AS_STRIDE + kb + 2 * tg);
                float2 p2 = *(const float2*)(As + r0 * AS_STRIDE + kb + 2 * tg + 8);
                float2 p3 = *(const float2*)(As + (r0 + 8) * AS_STRIDE + kb + 2 * tg + 8);
                split2(p0.x, p0.y, ah[mt][0], al[mt][0]);
                split2(p1.x, p1.y, ah[mt][1], al[mt][1]);
                split2(p2.x, p2.y, ah[mt][2], al[mt][2]);
                split2(p3.x, p3.y, ah[mt][3], al[mt][3]);
            }
#pragma unroll
            for (int nt = 0; nt < 4; ++nt) {
                int nb = wn + nt * 8 + g;
                unsigned bh[2], bl[2];
                float e0 = Bs[(kb + 2 * tg) * BS_STRIDE + nb];
                float e1 = Bs[(kb + 2 * tg + 1) * BS_STRIDE + nb];
                float e2 = Bs[(kb + 2 * tg + 8) * BS_STRIDE + nb];
                float e3 = Bs[(kb + 2 * tg + 9) * BS_STRIDE + nb];
                split2(e0, e1, bh[0], bl[0]);
                split2(e2, e3, bh[1], bl[1]);
#pragma unroll
                for (int mt = 0; mt < 2; ++mt) {
                    mma_bf16(c[mt][nt], ah[mt], bh);
                    mma_bf16(c[mt][nt], al[mt], bh);
                    mma_bf16(c[mt][nt], ah[mt], bl);
                }
            }
        }
        __syncthreads();
        if (kt + 1 < FIN / 32) {
#pragma unroll
            for (int p = 0; p < 4; ++p) {
                int i = p * 256 + tid, r = i >> 3, c4 = (i & 7) * 4;
                *(float4*)(As + r * AS_STRIDE + c4) = ra[p];
            }
#pragma unroll
            for (int p = 0; p < 2; ++p) {
                int i = p * 256 + tid, r = i >> 4, c4 = (i & 15) * 4;
                *(float4*)(Bs + r * BS_STRIDE + c4) = rb4[p];
            }
            __syncthreads();
        }
    }

#pragma unroll
    for (int mt = 0; mt < 2; ++mt)
#pragma unroll
        for (int nt = 0; nt < 4; ++nt) {
            int r0 = bm + wm + mt * 16 + g;
            int cc = wn + nt * 8 + 2 * tg;
            if (r0 < nrows)
                *(float2*)(g_buf1 + (size_t)r0 * HID + cc) =
                    make_float2(c[mt][nt][0], c[mt][nt][1]);
            if (r0 + 8 < nrows)
                *(float2*)(g_buf1 + (size_t)(r0 + 8) * HID + cc) =
                    make_float2(c[mt][nt][2], c[mt][nt][3]);
        }
}

// ------------------------------------------------- SpMM (64-wide): scatter-add
__global__ void spmm_hid(const int* __restrict__ er, const int* __restrict__ ec,
                         const float* __restrict__ ev, int E) {
    int gt = blockIdx.x * blockDim.x + threadIdx.x;
    int e = gt >> 4;
    if (e >= E) return;
    int s = (gt & 15) * 4;
    float v = __ldg(ev + e);
    int col = __ldg(ec + e);
    int row = __ldg(er + e);
    float4 a = *(const float4*)(g_buf1 + (size_t)col * HID + s);
    float4 d = make_float4(a.x * v, a.y * v, a.z * v, a.w * v);
#if __CUDA_ARCH__ >= 900
    atomicAdd((float4*)(g_buf2 + (size_t)row * HID + s), d);
#else
    float* p = g_buf2 + (size_t)row * HID + s;
    atomicAdd(p + 0, d.x); atomicAdd(p + 1, d.y);
    atomicAdd(p + 2, d.z); atomicAdd(p + 3, d.w);
#endif
}

// ---- JAX partitionable threefry (key=42): element j -> counts (0, j), fold = o0^o1
__device__ __forceinline__ unsigned tf_draw(unsigned j) {
    unsigned x0 = 0u, x1 = j;
    const unsigned ks0 = 0u, ks1 = 42u, ks2 = 0x1BD11BDAu ^ 42u;
    x0 += ks0; x1 += ks1;
#define TF_ROUND(r) { x0 += x1; x1 = __funnelshift_l(x1, x1, r); x1 ^= x0; }
    TF_ROUND(13) TF_ROUND(15) TF_ROUND(26) TF_ROUND(6)
    x0 += ks1; x1 += ks2 + 1u;
    TF_ROUND(17) TF_ROUND(29) TF_ROUND(16) TF_ROUND(24)
    x0 += ks2; x1 += ks0 + 2u;
    TF_ROUND(13) TF_ROUND(15) TF_ROUND(26) TF_ROUND(6)
    x0 += ks0; x1 += ks1 + 3u;
    TF_ROUND(17) TF_ROUND(29) TF_ROUND(16) TF_ROUND(24)
    x0 += ks1; x1 += ks2 + 4u;
    TF_ROUND(13) TF_ROUND(15) TF_ROUND(26) TF_ROUND(6)
    x0 += ks2; x1 += ks0 + 5u;
#undef TF_ROUND
    return x0 ^ x1;
}

// ---------------- GEMM2 fused with bias+relu+dropout: G = dropout(relu(spmm1+b1)) @ W2
__global__ __launch_bounds__(320) void gemm2_kernel(const float* __restrict__ W2,
                                                    const float* __restrict__ b1,
                                                    int nrows) {
    __shared__ float sH[128 * 68];
    __shared__ float sW[HID * NCLS];
    const int tid = threadIdx.x;
    const int bm = blockIdx.x * 128;
    for (int i = tid; i < HID * NCLS; i += 320) sW[i] = __ldg(W2 + i);
    for (int i = tid; i < 2048; i += 320) {
        int r = i >> 4, c4 = (i & 15) * 4, gr = bm + r;
        float4 v = make_float4(0.f, 0.f, 0.f, 0.f);
        if (gr < nrows) {
            v = *(const float4*)(g_buf2 + (size_t)gr * HID + c4);
            float4 bb = *(const float4*)(b1 + c4);
            unsigned j0 = (unsigned)gr * HID + c4;
            float t;
            t = fmaxf(v.x + bb.x, 0.f); v.x = (tf_draw(j0 + 0u) >> 31) ? 0.f : t * 2.f;
            t = fmaxf(v.y + bb.y, 0.f); v.y = (tf_draw(j0 + 1u) >> 31) ? 0.f : t * 2.f;
            t = fmaxf(v.z + bb.z, 0.f); v.z = (tf_draw(j0 + 2u) >> 31) ? 0.f : t * 2.f;
            t = fmaxf(v.w + bb.w, 0.f); v.w = (tf_draw(j0 + 3u) >> 31) ? 0.f : t * 2.f;
        }
        *(float4*)(sH + r * 68 + c4) = v;
    }
    __syncthreads();
    const int rg = tid / 10;
    const int cg = tid - rg * 10;
    float acc[4][4];
#pragma unroll
    for (int a = 0; a < 4; ++a)
#pragma unroll
        for (int b = 0; b < 4; ++b) acc[a][b] = 0.f;
#pragma unroll 8
    for (int k = 0; k < HID; ++k) {
        float4 w = *(const float4*)(sW + k * NCLS + cg * 4);
#pragma unroll
        for (int jr = 0; jr < 4; ++jr) {
            float a = sH[(rg * 4 + jr) * 68 + k];
            acc[jr][0] += a * w.x; acc[jr][1] += a * w.y;
            acc[jr][2] += a * w.z; acc[jr][3] += a * w.w;
        }
    }
#pragma unroll
    for (int jr = 0; jr < 4; ++jr) {
        int gr = bm + rg * 4 + jr;
        if (gr < nrows)
            *(float4*)(g_buf1 + (size_t)gr * NCLS + cg * 4) =
                make_float4(acc[jr][0], acc[jr][1], acc[jr][2], acc[jr][3]);
    }
}

// ------------------------------------------------- SpMM (40-wide): scatter-add
__global__ void spmm_cls(const int* __restrict__ er, const int* __restrict__ ec,
                         const float* __restrict__ ev, int E) {
    int gt = blockIdx.x * blockDim.x + threadIdx.x;
    int e = gt / 10;
    if (e >= E) return;
    int s = (gt - e * 10) * 4;
    float v = __ldg(ev + e);
    int col = __ldg(ec + e);
    int row = __ldg(er + e);
    float4 a = *(const float4*)(g_buf1 + (size_t)col * NCLS + s);
    float4 d = make_float4(a.x * v, a.y * v, a.z * v, a.w * v);
#if __CUDA_ARCH__ >= 900
    atomicAdd((float4*)(g_buf2 + (size_t)row * NCLS + s), d);
#else
    float* p = g_buf2 + (size_t)row * NCLS + s;
    atomicAdd(p + 0, d.x); atomicAdd(p + 1, d.y);
    atomicAdd(p + 2, d.z); atomicAdd(p + 3, d.w);
#endif
}

// ------------------------------------------------- +b2, log_softmax, write out
__global__ void lsm_kernel(const float* __restrict__ b2, float* __restrict__ out, int nrows) {
    int warp = threadIdx.x >> 5;
    int lane = threadIdx.x & 31;
    int row = blockIdx.x * 8 + warp;
    if (row >= nrows) return;
    const float* z = g_buf2 + (size_t)row * NCLS;
    float v0 = z[lane] + __ldg(b2 + lane);
    float v1 = -3.4e38f;
    if (lane < 8) v1 = z[32 + lane] + __ldg(b2 + 32 + lane);
    float m = fmaxf(v0, v1);
#pragma unroll
    for (int o = 16; o; o >>= 1) m = fmaxf(m, __shfl_xor_sync(0xffffffffu, m, o));
    float s = expf(v0 - m) + ((lane < 8) ? expf(v1 - m) : 0.f);
#pragma unroll
    for (int o = 16; o; o >>= 1) s += __shfl_xor_sync(0xffffffffu, s, o);
    float L = m + logf(s);
    out[(size_t)row * NCLS + lane] = v0 - L;
    if (lane < 8) out[(size_t)row * NCLS + 32 + lane] = v1 - L;
}

// ---------------------------------------------------------------- launcher
extern "C" void kernel_launch(void* const* d_in, const int* in_sizes, int n_in,
                              void* d_out, int out_size) {
    const float* x  = (const float*)d_in[0];
    const float* ev = (const float*)d_in[1];
    const float* W1 = (const float*)d_in[2];
    const float* b1 = (const float*)d_in[3];
    const float* W2 = (const float*)d_in[4];
    const float* b2 = (const float*)d_in[5];
    const int*   er = (const int*)d_in[6];
    const int*   ec = (const int*)d_in[7];
    const int nrows = in_sizes[0] / FIN;  // 100000
    const int E = in_sizes[1];            // 1000000
    float* out = (float*)d_out;

    int nh4 = nrows * HID / 4;
    zero_buf2<<<(nh4 + 255) / 256, 256>>>(nh4);
    gemm1_kernel<<<(nrows + 127) / 128, 256>>>(x, W1, nrows);
    spmm_hid<<<(E * 16 + 255) / 256, 256>>>(er, ec, ev, E);
    gemm2_kernel<<<(nrows + 127) / 128, 320>>>(W2, b1, nrows);
    int nc4 = nrows * NCLS / 4;
    zero_buf2<<<(nc4 + 255) / 256, 256>>>(nc4);
    spmm_cls<<<(E * 10 + 255) / 256, 256>>>(er, ec, ev, E);
    lsm_kernel<<<(nrows + 7) / 8, 256>>>(b2, out, nrows);
}

// round 10
// speedup vs baseline: 1.3704x; 1.0371x over previous
#include <cuda_runtime.h>

#define FIN 512
#define HID 64
#define NCLS 40
#define NMAX 100000
#define EMAX 1000000

// Scratch (no allocs allowed).
__device__ float g_buf1[6400000];
__device__ float g_buf2[6400000];
// CSR scratch
__device__ int   g_cnt[NMAX];
__device__ int   g_rowstart[NMAX + 1];
__device__ int   g_cursor[NMAX];
__device__ int   g_aux[1024];
__device__ int   g_auxs[1024];
__device__ int   g_csr_col[EMAX];
__device__ float g_csr_val[EMAX];

// ---------------------------------------------------------------- CSR build
__global__ void csr_zero_cnt(int n) {
    int i = blockIdx.x * blockDim.x + threadIdx.x;
    if (i < n) g_cnt[i] = 0;
}
__global__ void csr_hist(const int* __restrict__ er, int E) {
    int e = blockIdx.x * blockDim.x + threadIdx.x;
    if (e < E) atomicAdd(&g_cnt[__ldg(er + e)], 1);
}
// per-block sums of g_cnt -> g_aux[bid]
__global__ void csr_blocksum(int n) {
    __shared__ int sm[256];
    int i = blockIdx.x * 256 + threadIdx.x;
    int v = (i < n) ? g_cnt[i] : 0;
    sm[threadIdx.x] = v;
    __syncthreads();
    for (int o = 128; o; o >>= 1) {
        if (threadIdx.x < o) sm[threadIdx.x] += sm[threadIdx.x + o];
        __syncthreads();
    }
    if (threadIdx.x == 0) g_aux[blockIdx.x] = sm[0];
}
// single-block exclusive scan of g_aux[0..nb-1] -> g_auxs
__global__ void csr_scan_aux(int nb) {
    __shared__ int sm[1024];
    int t = threadIdx.x;
    int v = (t < nb) ? g_aux[t] : 0;
    sm[t] = v;
    __syncthreads();
    for (int o = 1; o < 1024; o <<= 1) {
        int a = (t >= o) ? sm[t - o] : 0;
        __syncthreads();
        sm[t] += a;
        __syncthreads();
    }
    if (t < nb) g_auxs[t] = sm[t] - v;  // exclusive
}
// per-block exclusive scan + base -> row_start, cursor
__global__ void csr_scan_final(int n, int E) {
    __shared__ int sm[256];
    int t = threadIdx.x;
    int i = blockIdx.x * 256 + t;
    int v = (i < n) ? g_cnt[i] : 0;
    sm[t] = v;
    __syncthreads();
    for (int o = 1; o < 256; o <<= 1) {
        int a = (t >= o) ? sm[t - o] : 0;
        __syncthreads();
        sm[t] += a;
        __syncthreads();
    }
    int base = g_auxs[blockIdx.x];
    int excl = base + sm[t] - v;
    if (i < n) {
        g_rowstart[i] = excl;
        g_cursor[i] = excl;
    }
    if (i == n - 1) g_rowstart[n] = E;
}
__global__ void csr_scatter(const int* __restrict__ er, const int* __restrict__ ec,
                            const float* __restrict__ ev, int E) {
    int e = blockIdx.x * blockDim.x + threadIdx.x;
    if (e >= E) return;
    int r = __ldg(er + e);
    int p = atomicAdd(&g_cursor[r], 1);
    g_csr_col[p] = __ldg(ec + e);
    g_csr_val[p] = __ldg(ev + e);
}

// ------------------------------------------------- GEMM1: Y = x @ W1  (bf16x3 tensor core)
__device__ __forceinline__ void mma_bf16(float c[4], const unsigned a[4], const unsigned b[2]) {
    asm volatile(
        "mma.sync.aligned.m16n8k16.row.col.f32.bf16.bf16.f32 "
        "{%0,%1,%2,%3}, {%4,%5,%6,%7}, {%8,%9}, {%0,%1,%2,%3};"
        : "+f"(c[0]), "+f"(c[1]), "+f"(c[2]), "+f"(c[3])
        : "r"(a[0]), "r"(a[1]), "r"(a[2]), "r"(a[3]), "r"(b[0]), "r"(b[1]));
}

__device__ __forceinline__ void split2(float ve, float vo, unsigned &h, unsigned &l) {
    unsigned hh;
    asm("cvt.rn.bf16x2.f32 %0, %1, %2;" : "=r"(hh) : "f"(vo), "f"(ve));
    float fe = __uint_as_float(hh << 16);
    float fo = __uint_as_float(hh & 0xffff0000u);
    float re = ve - fe;
    float ro = vo - fo;
    unsigned ll;
    asm("cvt.rn.bf16x2.f32 %0, %1, %2;" : "=r"(ll) : "f"(ro), "f"(re));
    h = hh; l = ll;
}

#define AS_STRIDE 36
#define BS_STRIDE 76

__global__ __launch_bounds__(256) void gemm1_kernel(const float* __restrict__ X,
                                                    const float* __restrict__ W,
                                                    int nrows) {
    __shared__ float As[128 * AS_STRIDE];
    __shared__ float Bs[32 * BS_STRIDE];
    const int tid = threadIdx.x;
    const int bm = blockIdx.x * 128;
    const int warp = tid >> 5, lane = tid & 31;
    const int g = lane >> 2, tg = lane & 3;
    const int wm = (warp >> 1) * 32;
    const int wn = (warp & 1) * 32;

    float c[2][4][4];
#pragma unroll
    for (int a = 0; a < 2; ++a)
#pragma unroll
        for (int b = 0; b < 4; ++b)
#pragma unroll
            for (int d = 0; d < 4; ++d) c[a][b][d] = 0.f;

    float4 ra[4], rb4[2];
#pragma unroll
    for (int p = 0; p < 4; ++p) {
        int i = p * 256 + tid, r = i >> 3, c4 = (i & 7) * 4, gr = bm + r;
        ra[p] = (gr < nrows) ? __ldg((const float4*)(X + (size_t)gr * FIN + c4))
                             : make_float4(0.f, 0.f, 0.f, 0.f);
    }
#pragma unroll
    for (int p = 0; p < 2; ++p) {
        int i = p * 256 + tid, r = i >> 4, c4 = (i & 15) * 4;
        rb4[p] = __ldg((const float4*)(W + (size_t)r * HID + c4));
    }
#pragma unroll
    for (int p = 0; p < 4; ++p) {
        int i = p * 256 + tid, r = i >> 3, c4 = (i & 7) * 4;
        *(float4*)(As + r * AS_STRIDE + c4) = ra[p];
    }
#pragma unroll
    for (int p = 0; p < 2; ++p) {
        int i = p * 256 + tid, r = i >> 4, c4 = (i & 15) * 4;
        *(float4*)(Bs + r * BS_STRIDE + c4) = rb4[p];
    }
    __syncthreads();

    for (int kt = 0; kt < FIN / 32; ++kt) {
        if (kt + 1 < FIN / 32) {
            int k0 = (kt + 1) * 32;
#pragma unroll
            for (int p = 0; p < 4; ++p) {
                int i = p * 256 + tid, r = i >> 3, c4 = (i & 7) * 4, gr = bm + r;
                ra[p] = (gr < nrows)
                            ? __ldg((const float4*)(X + (size_t)gr * FIN + k0 + c4))
                            : make_float4(0.f, 0.f, 0.f, 0.f);
            }
#pragma unroll
            for (int p = 0; p < 2; ++p) {
                int i = p * 256 + tid, r = i >> 4, c4 = (i & 15) * 4;
                rb4[p] = __ldg((const float4*)(W + (size_t)(k0 + r) * HID + c4));
            }
        }
#pragma unroll
        for (int kk = 0; kk < 2; ++kk) {
            const int kb = kk * 16;
            unsigned ah[2][4], al[2][4];
#pragma unroll
            for (int mt = 0; mt < 2; ++mt) {
                int r0 = wm + mt * 16 + g;
                float2 p0 = *(const float2*)(As + r0 * AS_STRIDE + kb + 2 * tg);
                float2 p1 = *(const float2*)(As + (r0 + 8) * AS_STRIDE + kb + 2 * tg);
                float2 p2 = *(const float2*)(As + r0 * AS_STRIDE + kb + 2 * tg + 8);
                float2 p3 = *(const float2*)(As + (r0 + 8) * AS_STRIDE + kb + 2 * tg + 8);
                split2(p0.x, p0.y, ah[mt][0], al[mt][0]);
                split2(p1.x, p1.y, ah[mt][1], al[mt][1]);
                split2(p2.x, p2.y, ah[mt][2], al[mt][2]);
                split2(p3.x, p3.y, ah[mt][3], al[mt][3]);
            }
#pragma unroll
            for (int nt = 0; nt < 4; ++nt) {
                int nb = wn + nt * 8 + g;
                unsigned bh[2], bl[2];
                float e0 = Bs[(kb + 2 * tg) * BS_STRIDE + nb];
                float e1 = Bs[(kb + 2 * tg + 1) * BS_STRIDE + nb];
                float e2 = Bs[(kb + 2 * tg + 8) * BS_STRIDE + nb];
                float e3 = Bs[(kb + 2 * tg + 9) * BS_STRIDE + nb];
                split2(e0, e1, bh[0], bl[0]);
                split2(e2, e3, bh[1], bl[1]);
#pragma unroll
                for (int mt = 0; mt < 2; ++mt) {
                    mma_bf16(c[mt][nt], ah[mt], bh);
                    mma_bf16(c[mt][nt], al[mt], bh);
                    mma_bf16(c[mt][nt], ah[mt], bl);
                }
            }
        }
        __syncthreads();
        if (kt + 1 < FIN / 32) {
#pragma unroll
            for (int p = 0; p < 4; ++p) {
                int i = p * 256 + tid, r = i >> 3, c4 = (i & 7) * 4;
                *(float4*)(As + r * AS_STRIDE + c4) = ra[p];
            }
#pragma unroll
            for (int p = 0; p < 2; ++p) {
                int i = p * 256 + tid, r = i >> 4, c4 = (i & 15) * 4;
                *(float4*)(Bs + r * BS_STRIDE + c4) = rb4[p];
            }
            __syncthreads();
        }
    }

#pragma unroll
    for (int mt = 0; mt < 2; ++mt)
#pragma unroll
        for (int nt = 0; nt < 4; ++nt) {
            int r0 = bm + wm + mt * 16 + g;
            int cc = wn + nt * 8 + 2 * tg;
            if (r0 < nrows)
                *(float2*)(g_buf1 + (size_t)r0 * HID + cc) =
                    make_float2(c[mt][nt][0], c[mt][nt][1]);
            if (r0 + 8 < nrows)
                *(float2*)(g_buf1 + (size_t)(r0 + 8) * HID + cc) =
                    make_float2(c[mt][nt][2], c[mt][nt][3]);
        }
}

// ------------------------- SpMM1 gather: one warp per row, 64 feats (2/lane)
__global__ __launch_bounds__(256) void spmm1_gather(int nrows) {
    int warp = threadIdx.x >> 5;
    int lane = threadIdx.x & 31;
    int row = blockIdx.x * 8 + warp;
    if (row >= nrows) return;
    int s = g_rowstart[row], e = g_rowstart[row + 1];
    float a0 = 0.f, a1 = 0.f;
    int l2 = lane * 2;
    for (int i = s; i < e; ++i) {
        int c = g_csr_col[i];
        float v = g_csr_val[i];
        float2 f = *(const float2*)(g_buf1 + (size_t)c * HID + l2);
        a0 += v * f.x;
        a1 += v * f.y;
    }
    *(float2*)(g_buf2 + (size_t)row * HID + l2) = make_float2(a0, a1);
}

// ---- JAX partitionable threefry (key=42): element j -> counts (0, j), fold = o0^o1
__device__ __forceinline__ unsigned tf_draw(unsigned j) {
    unsigned x0 = 0u, x1 = j;
    const unsigned ks0 = 0u, ks1 = 42u, ks2 = 0x1BD11BDAu ^ 42u;
    x0 += ks0; x1 += ks1;
#define TF_ROUND(r) { x0 += x1; x1 = __funnelshift_l(x1, x1, r); x1 ^= x0; }
    TF_ROUND(13) TF_ROUND(15) TF_ROUND(26) TF_ROUND(6)
    x0 += ks1; x1 += ks2 + 1u;
    TF_ROUND(17) TF_ROUND(29) TF_ROUND(16) TF_ROUND(24)
    x0 += ks2; x1 += ks0 + 2u;
    TF_ROUND(13) TF_ROUND(15) TF_ROUND(26) TF_ROUND(6)
    x0 += ks0; x1 += ks1 + 3u;
    TF_ROUND(17) TF_ROUND(29) TF_ROUND(16) TF_ROUND(24)
    x0 += ks1; x1 += ks2 + 4u;
    TF_ROUND(13) TF_ROUND(15) TF_ROUND(26) TF_ROUND(6)
    x0 += ks2; x1 += ks0 + 5u;
#undef TF_ROUND
    return x0 ^ x1;
}

// ---------------- GEMM2 fused with bias+relu+dropout: G = dropout(relu(spmm1+b1)) @ W2
__global__ __launch_bounds__(320) void gemm2_kernel(const float* __restrict__ W2,
                                                    const float* __restrict__ b1,
                                                    int nrows) {
    __shared__ float sH[128 * 68];
    __shared__ float sW[HID * NCLS];
    const int tid = threadIdx.x;
    const int bm = blockIdx.x * 128;
    for (int i = tid; i < HID * NCLS; i += 320) sW[i] = __ldg(W2 + i);
    for (int i = tid; i < 2048; i += 320) {
        int r = i >> 4, c4 = (i & 15) * 4, gr = bm + r;
        float4 v = make_float4(0.f, 0.f, 0.f, 0.f);
        if (gr < nrows) {
            v = *(const float4*)(g_buf2 + (size_t)gr * HID + c4);
            float4 bb = *(const float4*)(b1 + c4);
            unsigned j0 = (unsigned)gr * HID + c4;
            float t;
            t = fmaxf(v.x + bb.x, 0.f); v.x = (tf_draw(j0 + 0u) >> 31) ? 0.f : t * 2.f;
            t = fmaxf(v.y + bb.y, 0.f); v.y = (tf_draw(j0 + 1u) >> 31) ? 0.f : t * 2.f;
            t = fmaxf(v.z + bb.z, 0.f); v.z = (tf_draw(j0 + 2u) >> 31) ? 0.f : t * 2.f;
            t = fmaxf(v.w + bb.w, 0.f); v.w = (tf_draw(j0 + 3u) >> 31) ? 0.f : t * 2.f;
        }
        *(float4*)(sH + r * 68 + c4) = v;
    }
    __syncthreads();
    const int rg = tid / 10;
    const int cg = tid - rg * 10;
    float acc[4][4];
#pragma unroll
    for (int a = 0; a < 4; ++a)
#pragma unroll
        for (int b = 0; b < 4; ++b) acc[a][b] = 0.f;
#pragma unroll 8
    for (int k = 0; k < HID; ++k) {
        float4 w = *(const float4*)(sW + k * NCLS + cg * 4);
#pragma unroll
        for (int jr = 0; jr < 4; ++jr) {
            float a = sH[(rg * 4 + jr) * 68 + k];
            acc[jr][0] += a * w.x; acc[jr][1] += a * w.y;
            acc[jr][2] += a * w.z; acc[jr][3] += a * w.w;
        }
    }
#pragma unroll
    for (int jr = 0; jr < 4; ++jr) {
        int gr = bm + rg * 4 + jr;
        if (gr < nrows)
            *(float4*)(g_buf1 + (size_t)gr * NCLS + cg * 4) =
                make_float4(acc[jr][0], acc[jr][1], acc[jr][2], acc[jr][3]);
    }
}

// ------- SpMM2 gather fused with +b2 and log_softmax: one warp per row
__global__ __launch_bounds__(256) void spmm2_lsm(const float* __restrict__ b2,
                                                 float* __restrict__ out, int nrows) {
    int warp = threadIdx.x >> 5;
    int lane = threadIdx.x & 31;
    int row = blockIdx.x * 8 + warp;
    if (row >= nrows) return;
    int s = g_rowstart[row], e = g_rowstart[row + 1];
    bool act = lane < 20;
    int l2 = lane * 2;
    float a0 = 0.f, a1 = 0.f;
    for (int i = s; i < e; ++i) {
        int c = g_csr_col[i];
        float v = g_csr_val[i];
        if (act) {
            float2 f = *(const float2*)(g_buf1 + (size_t)c * NCLS + l2);
            a0 += v * f.x;
            a1 += v * f.y;
        }
    }
    if (act) {
        a0 += __ldg(b2 + l2);
        a1 += __ldg(b2 + l2 + 1);
    } else {
        a0 = a1 = -3.4e38f;
    }
    float m = fmaxf(a0, a1);
#pragma unroll
    for (int o = 16; o; o >>= 1) m = fmaxf(m, __shfl_xor_sync(0xffffffffu, m, o));
    float sum = act ? (expf(a0 - m) + expf(a1 - m)) : 0.f;
#pragma unroll
    for (int o = 16; o; o >>= 1) sum += __shfl_xor_sync(0xffffffffu, sum, o);
    float L = m + logf(sum);
    if (act)
        *(float2*)(out + (size_t)row * NCLS + l2) = make_float2(a0 - L, a1 - L);
}

// ---------------------------------------------------------------- launcher
extern "C" void kernel_launch(void* const* d_in, const int* in_sizes, int n_in,
                              void* d_out, int out_size) {
    const float* x  = (const float*)d_in[0];
    const float* ev = (const float*)d_in[1];
    const float* W1 = (const float*)d_in[2];
    const float* b1 = (const float*)d_in[3];
    const float* W2 = (const float*)d_in[4];
    const float* b2 = (const float*)d_in[5];
    const int*   er = (const int*)d_in[6];
    const int*   ec = (const int*)d_in[7];
    const int nrows = in_sizes[0] / FIN;  // 100000
    const int E = in_sizes[1];            // 1000000
    float* out = (float*)d_out;

    const int NB = (nrows + 255) / 256;   // 391 scan blocks
    // ---- CSR build (per-launch, deterministic up to float sum order)
    csr_zero_cnt<<<NB, 256>>>(nrows);
    csr_hist<<<(E + 255) / 256, 256>>>(er, E);
    csr_blocksum<<<NB, 256>>>(nrows);
    csr_scan_aux<<<1, 1024>>>(NB);
    csr_scan_final<<<NB, 256>>>(nrows, E);
    csr_scatter<<<(E + 255) / 256, 256>>>(er, ec, ev, E);
    // ---- pipeline
    gemm1_kernel<<<(nrows + 127) / 128, 256>>>(x, W1, nrows);
    spmm1_gather<<<(nrows + 7) / 8, 256>>>(nrows);
    gemm2_kernel<<<(nrows + 127) / 128, 320>>>(W2, b1, nrows);
    spmm2_lsm<<<(nrows + 7) / 8, 256>>>(b2, out, nrows);
}

// round 15
// speedup vs baseline: 1.4935x; 1.0898x over previous
#include <cuda_runtime.h>
#include <cuda_bf16.h>
#include <cstdint>

#define FIN 512
#define HID 64
#define NCLS 40
#define NMAX 100000
#define EMAX 1000000

// Scratch (no allocs allowed).
__device__ float g_buf1[6400000];
__device__ float g_buf2[6400000];
__device__ int   g_cnt[NMAX];
__device__ int   g_rowstart[NMAX + 1];
__device__ int   g_cursor[NMAX];
__device__ int   g_aux[1024];
__device__ int   g_auxs[1024];
__device__ int   g_csr_col[EMAX];
__device__ float g_csr_val[EMAX];

// ======================================================== CSR build
__global__ void csr_zero_cnt(int n) {
    int i = blockIdx.x * blockDim.x + threadIdx.x;
    if (i < n) g_cnt[i] = 0;
}
__global__ void csr_hist(const int* __restrict__ er, int E) {
    int e = blockIdx.x * blockDim.x + threadIdx.x;
    if (e < E) atomicAdd(&g_cnt[__ldg(er + e)], 1);
}
__global__ void csr_blocksum(int n) {
    __shared__ int sm[256];
    int i = blockIdx.x * 256 + threadIdx.x;
    int v = (i < n) ? g_cnt[i] : 0;
    sm[threadIdx.x] = v;
    __syncthreads();
    for (int o = 128; o; o >>= 1) {
        if (threadIdx.x < o) sm[threadIdx.x] += sm[threadIdx.x + o];
        __syncthreads();
    }
    if (threadIdx.x == 0) g_aux[blockIdx.x] = sm[0];
}
__global__ void csr_scan_aux(int nb) {
    __shared__ int sm[1024];
    int t = threadIdx.x;
    int v = (t < nb) ? g_aux[t] : 0;
    sm[t] = v;
    __syncthreads();
    for (int o = 1; o < 1024; o <<= 1) {
        int a = (t >= o) ? sm[t - o] : 0;
        __syncthreads();
        sm[t] += a;
        __syncthreads();
    }
    if (t < nb) g_auxs[t] = sm[t] - v;
}
__global__ void csr_scan_final(int n, int E) {
    __shared__ int sm[256];
    int t = threadIdx.x;
    int i = blockIdx.x * 256 + t;
    int v = (i < n) ? g_cnt[i] : 0;
    sm[t] = v;
    __syncthreads();
    for (int o = 1; o < 256; o <<= 1) {
        int a = (t >= o) ? sm[t - o] : 0;
        __syncthreads();
        sm[t] += a;
        __syncthreads();
    }
    int base = g_auxs[blockIdx.x];
    int excl = base + sm[t] - v;
    if (i < n) {
        g_rowstart[i] = excl;
        g_cursor[i] = excl;
    }
    if (i == n - 1) g_rowstart[n] = E;
}
__global__ void csr_scatter(const int* __restrict__ er, const int* __restrict__ ec,
                            const float* __restrict__ ev, int E) {
    int e = blockIdx.x * blockDim.x + threadIdx.x;
    if (e >= E) return;
    int r = __ldg(er + e);
    int p = atomicAdd(&g_cursor[r], 1);
    g_csr_col[p] = __ldg(ec + e);
    g_csr_val[p] = __ldg(ev + e);
}

// ============ GEMM1: Y = x @ W1 (mma.sync bf16x3, preconverted hi/lo smem)
__device__ __forceinline__ void mma_bf16(float c[4], const unsigned a[4], const unsigned b[2]) {
    asm volatile(
        "mma.sync.aligned.m16n8k16.row.col.f32.bf16.bf16.f32 "
        "{%0,%1,%2,%3}, {%4,%5,%6,%7}, {%8,%9}, {%0,%1,%2,%3};"
        : "+f"(c[0]), "+f"(c[1]), "+f"(c[2]), "+f"(c[3])
        : "r"(a[0]), "r"(a[1]), "r"(a[2]), "r"(a[3]), "r"(b[0]), "r"(b[1]));
}
// pack (even,odd) fp32 pair into bf16x2 hi + bf16x2 lo (residual)
__device__ __forceinline__ void split2(float ve, float vo, unsigned &h, unsigned &l) {
    unsigned hh;
    asm("cvt.rn.bf16x2.f32 %0, %1, %2;" : "=r"(hh) : "f"(vo), "f"(ve));
    float fe = __uint_as_float(hh << 16);
    float fo = __uint_as_float(hh & 0xffff0000u);
    float re = ve - fe;
    float ro = vo - fo;
    unsigned ll;
    asm("cvt.rn.bf16x2.f32 %0, %1, %2;" : "=r"(ll) : "f"(ro), "f"(re));
    h = hh; l = ll;
}

#define ASTR 20  // uint32 stride per row (16 kpairs + 4 pad): conflict-free compute loads

__global__ __launch_bounds__(256) void gemm1_kernel(const float* __restrict__ X,
                                                    const float* __restrict__ W,
                                                    int nrows) {
    __shared__ unsigned Ah[128 * ASTR], Al[128 * ASTR];
    __shared__ unsigned Bh[64 * ASTR],  Bl[64 * ASTR];
    const int tid = threadIdx.x;
    const int bm = blockIdx.x * 128;
    const int warp = tid >> 5, lane = tid & 31;
    const int g = lane >> 2, tg = lane & 3;
    const int wm = (warp >> 1) * 32;
    const int wn = (warp & 1) * 32;
    const int bn = tid & 63;              // B n this thread loads
    const int bkp0 = tid >> 6;            // B kpair sub-index (0..3)

    float c[2][4][4];
#pragma unroll
    for (int a = 0; a < 2; ++a)
#pragma unroll
        for (int b = 0; b < 4; ++b)
#pragma unroll
            for (int d = 0; d < 4; ++d) c[a][b][d] = 0.f;

    float4 ra[4];   // FIX: 4 pages -> full 128 rows x 32 k
    float rb[8];
    // prologue: raw loads for tile kt=0
#pragma unroll
    for (int p = 0; p < 4; ++p) {
        int i = p * 256 + tid;
        int gr = bm + (i >> 3);
        int kq = (i & 7) * 4;
        ra[p] = (gr < nrows) ? __ldg((const float4*)(X + (size_t)gr * FIN + kq))
                             : make_float4(0.f, 0.f, 0.f, 0.f);
    }
#pragma unroll
    for (int it = 0; it < 4; ++it) {
        int kp = it * 4 + bkp0;
        rb[2 * it]     = __ldg(W + (size_t)(2 * kp) * HID + bn);
        rb[2 * it + 1] = __ldg(W + (size_t)(2 * kp + 1) * HID + bn);
    }

    for (int kt = 0; kt < FIN / 32; ++kt) {
        // convert + store current tile
#pragma unroll
        for (int p = 0; p < 4; ++p) {
            int i = p * 256 + tid;
            int r = i >> 3;
            int kq = (i & 7) * 4;
            unsigned h0, l0, h1, l1;
            split2(ra[p].x, ra[p].y, h0, l0);
            split2(ra[p].z, ra[p].w, h1, l1);
            int o = r * ASTR + kq / 2;
            Ah[o] = h0; Ah[o + 1] = h1;
            Al[o] = l0; Al[o + 1] = l1;
        }
#pragma unroll
        for (int it = 0; it < 4; ++it) {
            int kp = it * 4 + bkp0;
            unsigned h, l;
            split2(rb[2 * it], rb[2 * it + 1], h, l);
            Bh[bn * ASTR + kp] = h;
            Bl[bn * ASTR + kp] = l;
        }
        __syncthreads();
        // prefetch next tile raw
        if (kt + 1 < FIN / 32) {
            int k0 = (kt + 1) * 32;
#pragma unroll
            for (int p = 0; p < 4; ++p) {
                int i = p * 256 + tid;
                int gr = bm + (i >> 3);
                int kq = (i & 7) * 4;
                ra[p] = (gr < nrows) ? __ldg((const float4*)(X + (size_t)gr * FIN + k0 + kq))
                                     : make_float4(0.f, 0.f, 0.f, 0.f);
            }
#pragma unroll
            for (int it = 0; it < 4; ++it) {
                int kp = it * 4 + bkp0;
                rb[2 * it]     = __ldg(W + (size_t)(k0 + 2 * kp) * HID + bn);
                rb[2 * it + 1] = __ldg(W + (size_t)(k0 + 2 * kp + 1) * HID + bn);
            }
        }
        // compute: 2 x k16
#pragma unroll
        for (int kk = 0; kk < 2; ++kk) {
            const int kb = kk * 8;
            unsigned ah[2][4], al[2][4];
#pragma unroll
            for (int mt = 0; mt < 2; ++mt) {
                int r0 = (wm + mt * 16 + g) * ASTR + kb + tg;
                ah[mt][0] = Ah[r0];                al[mt][0] = Al[r0];
                ah[mt][1] = Ah[r0 + 8 * ASTR];     al[mt][1] = Al[r0 + 8 * ASTR];
                ah[mt][2] = Ah[r0 + 4];            al[mt][2] = Al[r0 + 4];
                ah[mt][3] = Ah[r0 + 8 * ASTR + 4]; al[mt][3] = Al[r0 + 8 * ASTR + 4];
            }
#pragma unroll
            for (int nt = 0; nt < 4; ++nt) {
                int nb0 = (wn + nt * 8 + g) * ASTR + kb + tg;
                unsigned bh[2], bl[2];
                bh[0] = Bh[nb0];     bh[1] = Bh[nb0 + 4];
                bl[0] = Bl[nb0];     bl[1] = Bl[nb0 + 4];
#pragma unroll
                for (int mt = 0; mt < 2; ++mt) {
                    mma_bf16(c[mt][nt], ah[mt], bh);
                    mma_bf16(c[mt][nt], al[mt], bh);
                    mma_bf16(c[mt][nt], ah[mt], bl);
                }
            }
        }
        __syncthreads();
    }

#pragma unroll
    for (int mt = 0; mt < 2; ++mt)
#pragma unroll
        for (int nt = 0; nt < 4; ++nt) {
            int r0 = bm + wm + mt * 16 + g;
            int cc = wn + nt * 8 + 2 * tg;
            if (r0 < nrows)
                *(float2*)(g_buf1 + (size_t)r0 * HID + cc) =
                    make_float2(c[mt][nt][0], c[mt][nt][1]);
            if (r0 + 8 < nrows)
                *(float2*)(g_buf1 + (size_t)(r0 + 8) * HID + cc) =
                    make_float2(c[mt][nt][2], c[mt][nt][3]);
        }
}

// ---- JAX partitionable threefry (key=42): element j -> counts (0, j), fold = o0^o1
__device__ __forceinline__ unsigned tf_draw(unsigned j) {
    unsigned x0 = 0u, x1 = j;
    const unsigned ks0 = 0u, ks1 = 42u, ks2 = 0x1BD11BDAu ^ 42u;
    x0 += ks0; x1 += ks1;
#define TF_ROUND(r) { x0 += x1; x1 = __funnelshift_l(x1, x1, r); x1 ^= x0; }
    TF_ROUND(13) TF_ROUND(15) TF_ROUND(26) TF_ROUND(6)
    x0 += ks1; x1 += ks2 + 1u;
    TF_ROUND(17) TF_ROUND(29) TF_ROUND(16) TF_ROUND(24)
    x0 += ks2; x1 += ks0 + 2u;
    TF_ROUND(13) TF_ROUND(15) TF_ROUND(26) TF_ROUND(6)
    x0 += ks0; x1 += ks1 + 3u;
    TF_ROUND(17) TF_ROUND(29) TF_ROUND(16) TF_ROUND(24)
    x0 += ks1; x1 += ks2 + 4u;
    TF_ROUND(13) TF_ROUND(15) TF_ROUND(26) TF_ROUND(6)
    x0 += ks2; x1 += ks0 + 5u;
#undef TF_ROUND
    return x0 ^ x1;
}

// ---- SpMM1 gather + bias + relu + dropout epilogue: one warp per row, MLP-2
__global__ __launch_bounds__(256) void spmm1_gather(const float* __restrict__ b1, int nrows) {
    int warp = threadIdx.x >> 5;
    int lane = threadIdx.x & 31;
    int row = blockIdx.x * 8 + warp;
    if (row >= nrows) return;
    int s = g_rowstart[row], e = g_rowstart[row + 1];
    float a0 = 0.f, a1 = 0.f;
    int l2 = lane * 2;
    int i = s;
    for (; i + 1 < e; i += 2) {
        int c0 = g_csr_col[i], c1 = g_csr_col[i + 1];
        float v0 = g_csr_val[i], v1 = g_csr_val[i + 1];
        float2 f0 = *(const float2*)(g_buf1 + (size_t)c0 * HID + l2);
        float2 f1 = *(const float2*)(g_buf1 + (size_t)c1 * HID + l2);
        a0 += v0 * f0.x + v1 * f1.x;
        a1 += v0 * f0.y + v1 * f1.y;
    }
    if (i < e) {
        int c0 = g_csr_col[i];
        float v0 = g_csr_val[i];
        float2 f0 = *(const float2*)(g_buf1 + (size_t)c0 * HID + l2);
        a0 += v0 * f0.x;
        a1 += v0 * f0.y;
    }
    float2 bb = *(const float2*)(b1 + l2);
    unsigned j0 = (unsigned)row * HID + l2;
    a0 = fmaxf(a0 + bb.x, 0.f);
    a0 = (tf_draw(j0) >> 31) ? 0.f : a0 * 2.f;
    a1 = fmaxf(a1 + bb.y, 0.f);
    a1 = (tf_draw(j0 + 1u) >> 31) ? 0.f : a1 * 2.f;
    *(float2*)(g_buf2 + (size_t)row * HID + l2) = make_float2(a0, a1);
}

// ---------------- GEMM2: G = h @ W2 (h already bias/relu/dropout'd)
__global__ __launch_bounds__(320) void gemm2_kernel(const float* __restrict__ W2, int nrows) {
    __shared__ float sH[128 * 68];
    __shared__ float sW[HID * NCLS];
    const int tid = threadIdx.x;
    const int bm = blockIdx.x * 128;
    for (int i = tid; i < HID * NCLS; i += 320) sW[i] = __ldg(W2 + i);
    for (int i = tid; i < 2048; i += 320) {
        int r = i >> 4, c4 = (i & 15) * 4, gr = bm + r;
        float4 v = (gr < nrows) ? *(const float4*)(g_buf2 + (size_t)gr * HID + c4)
                                : make_float4(0.f, 0.f, 0.f, 0.f);
        *(float4*)(sH + r * 68 + c4) = v;
    }
    __syncthreads();
    const int rg = tid / 10;
    const int cg = tid - rg * 10;
    float acc[4][4];
#pragma unroll
    for (int a = 0; a < 4; ++a)
#pragma unroll
        for (int b = 0; b < 4; ++b) acc[a][b] = 0.f;
#pragma unroll 8
    for (int k = 0; k < HID; ++k) {
        float4 w = *(const float4*)(sW + k * NCLS + cg * 4);
#pragma unroll
        for (int jr = 0; jr < 4; ++jr) {
            float a = sH[(rg * 4 + jr) * 68 + k];
            acc[jr][0] += a * w.x; acc[jr][1] += a * w.y;
            acc[jr][2] += a * w.z; acc[jr][3] += a * w.w;
        }
    }
#pragma unroll
    for (int jr = 0; jr < 4; ++jr) {
        int gr = bm + rg * 4 + jr;
        if (gr < nrows)
            *(float4*)(g_buf1 + (size_t)gr * NCLS + cg * 4) =
                make_float4(acc[jr][0], acc[jr][1], acc[jr][2], acc[jr][3]);
    }
}

// ------- SpMM2 gather fused with +b2 and log_softmax: one warp per row, MLP-2
__global__ __launch_bounds__(256) void spmm2_lsm(const float* __restrict__ b2,
                                                 float* __restrict__ out, int nrows) {
    int warp = threadIdx.x >> 5;
    int lane = threadIdx.x & 31;
    int row = blockIdx.x * 8 + warp;
    if (row >= nrows) return;
    int s = g_rowstart[row], e = g_rowstart[row + 1];
    bool act = lane < 20;
    int l2 = lane * 2;
    float a0 = 0.f, a1 = 0.f;
    int i = s;
    for (; i + 1 < e; i += 2) {
        int c0 = g_csr_col[i], c1 = g_csr_col[i + 1];
        float v0 = g_csr_val[i], v1 = g_csr_val[i + 1];
        if (act) {
            float2 f0 = *(const float2*)(g_buf1 + (size_t)c0 * NCLS + l2);
            float2 f1 = *(const float2*)(g_buf1 + (size_t)c1 * NCLS + l2);
            a0 += v0 * f0.x + v1 * f1.x;
            a1 += v0 * f0.y + v1 * f1.y;
        }
    }
    if (i < e) {
        int c0 = g_csr_col[i];
        float v0 = g_csr_val[i];
        if (act) {
            float2 f0 = *(const float2*)(g_buf1 + (size_t)c0 * NCLS + l2);
            a0 += v0 * f0.x;
            a1 += v0 * f0.y;
        }
    }
    if (act) {
        a0 += __ldg(b2 + l2);
        a1 += __ldg(b2 + l2 + 1);
    } else {
        a0 = a1 = -3.4e38f;
    }
    float m = fmaxf(a0, a1);
#pragma unroll
    for (int o = 16; o; o >>= 1) m = fmaxf(m, __shfl_xor_sync(0xffffffffu, m, o));
    float sum = act ? (expf(a0 - m) + expf(a1 - m)) : 0.f;
#pragma unroll
    for (int o = 16; o; o >>= 1) sum += __shfl_xor_sync(0xffffffffu, sum, o);
    float L = m + logf(sum);
    if (act)
        *(float2*)(out + (size_t)row * NCLS + l2) = make_float2(a0 - L, a1 - L);
}

// ---------------------------------------------------------------- launcher
extern "C" void kernel_launch(void* const* d_in, const int* in_sizes, int n_in,
                              void* d_out, int out_size) {
    const float* x  = (const float*)d_in[0];
    const float* ev = (const float*)d_in[1];
    const float* W1 = (const float*)d_in[2];
    const float* b1 = (const float*)d_in[3];
    const float* W2 = (const float*)d_in[4];
    const float* b2 = (const float*)d_in[5];
    const int*   er = (const int*)d_in[6];
    const int*   ec = (const int*)d_in[7];
    const int nrows = in_sizes[0] / FIN;  // 100000
    const int E = in_sizes[1];            // 1000000
    float* out = (float*)d_out;

    const int NB = (nrows + 255) / 256;
    // launch index 3 (ncu capture slot) = gemm1_kernel
    csr_zero_cnt<<<NB, 256>>>(nrows);
    csr_hist<<<(E + 255) / 256, 256>>>(er, E);
    csr_blocksum<<<NB, 256>>>(nrows);
    gemm1_kernel<<<(nrows + 127) / 128, 256>>>(x, W1, nrows);
    csr_scan_aux<<<1, 1024>>>(NB);
    csr_scan_final<<<NB, 256>>>(nrows, E);
    csr_scatter<<<(E + 255) / 256, 256>>>(er, ec, ev, E);
    spmm1_gather<<<(nrows + 7) / 8, 256>>>(b1, nrows);
    gemm2_kernel<<<(nrows + 127) / 128, 320>>>(W2, nrows);
    spmm2_lsm<<<(nrows + 7) / 8, 256>>>(b2, out, nrows);
}